// round 5
// baseline (speedup 1.0000x reference)
#include <cuda_runtime.h>
#include <cuda_bf16.h>
#include <cstdint>
#include <math.h>

// Problem constants
#define BB 2
#define NN 2048
#define CC 1024
#define HH 16
#define HD 64
#define GH 256
#define C3 3072
#define TOK (BB*NN)   // 4096

// Scratch (device globals: allocation-free). bf16 hi/lo split everywhere.
__device__ __nv_bfloat16 g_xh[(size_t)TOK * CC],  g_xl[(size_t)TOK * CC];
__device__ __nv_bfloat16 g_wqh[(size_t)C3 * CC],  g_wql[(size_t)C3 * CC];
__device__ __nv_bfloat16 g_wph[(size_t)CC * CC],  g_wpl[(size_t)CC * CC];
__device__ __nv_bfloat16 g_qh[(size_t)TOK * C3],  g_ql[(size_t)TOK * C3];
__device__ __nv_bfloat16 g_ath[(size_t)TOK * CC], g_atl[(size_t)TOK * CC];
__device__ float g_gate[TOK];

// ---------------------------------------------------------------------------
// Helpers (baseline PTX: ldmatrix sm_75, mma.sync bf16 sm_80, cp.async sm_80)
// ---------------------------------------------------------------------------
__device__ __forceinline__ uint32_t smem_u32(const void* p) {
    uint32_t a;
    asm("{ .reg .u64 t; cvta.to.shared.u64 t, %1; cvt.u32.u64 %0, t; }"
        : "=r"(a) : "l"(p));
    return a;
}
__device__ __forceinline__ void ldsm4(uint32_t* r, uint32_t addr) {
    asm volatile("ldmatrix.sync.aligned.m8n8.x4.shared.b16 {%0,%1,%2,%3}, [%4];"
                 : "=r"(r[0]), "=r"(r[1]), "=r"(r[2]), "=r"(r[3]) : "r"(addr));
}
__device__ __forceinline__ void ldsm4t(uint32_t* r, uint32_t addr) {
    asm volatile("ldmatrix.sync.aligned.m8n8.x4.trans.shared.b16 {%0,%1,%2,%3}, [%4];"
                 : "=r"(r[0]), "=r"(r[1]), "=r"(r[2]), "=r"(r[3]) : "r"(addr));
}
__device__ __forceinline__ void mma16816(float* d, const uint32_t* a,
                                         uint32_t b0, uint32_t b1) {
    asm volatile(
        "mma.sync.aligned.m16n8k16.row.col.f32.bf16.bf16.f32 "
        "{%0,%1,%2,%3}, {%4,%5,%6,%7}, {%8,%9}, {%0,%1,%2,%3};"
        : "+f"(d[0]), "+f"(d[1]), "+f"(d[2]), "+f"(d[3])
        : "r"(a[0]), "r"(a[1]), "r"(a[2]), "r"(a[3]), "r"(b0), "r"(b1));
}
__device__ __forceinline__ void cpa16(uint32_t dst, const void* src) {
    asm volatile("cp.async.cg.shared.global [%0], [%1], 16;"
                 :: "r"(dst), "l"(src) : "memory");
}
__device__ __forceinline__ void cpa_commit() {
    asm volatile("cp.async.commit_group;" ::: "memory");
}
template <int N>
__device__ __forceinline__ void cpa_wait() {
    asm volatile("cp.async.wait_group %0;" :: "n"(N) : "memory");
}
// Split (x,y) fp32 pair into bf16x2 hi + bf16x2 lo
__device__ __forceinline__ void pack2(float x, float y, uint32_t& hi, uint32_t& lo) {
    __nv_bfloat162 h = __floats2bfloat162_rn(x, y);
    float2 hf = __bfloat1622float2(h);
    __nv_bfloat162 l = __floats2bfloat162_rn(x - hf.x, y - hf.y);
    hi = *reinterpret_cast<uint32_t*>(&h);
    lo = *reinterpret_cast<uint32_t*>(&l);
}
__device__ __forceinline__ void split4(float4 v, uint32_t& h0, uint32_t& h1,
                                       uint32_t& l0, uint32_t& l1) {
    pack2(v.x, v.y, h0, l0);
    pack2(v.z, v.w, h1, l1);
}

// ---------------------------------------------------------------------------
// Pre-split: fp32 -> bf16 hi/lo
// ---------------------------------------------------------------------------
__global__ void split_kernel(const float* __restrict__ s,
                             __nv_bfloat16* __restrict__ h,
                             __nv_bfloat16* __restrict__ l, int n4) {
    int i = blockIdx.x * blockDim.x + threadIdx.x;
    if (i >= n4) return;
    float4 v = ((const float4*)s)[i];
    uint32_t h0, h1, l0, l1;
    split4(v, h0, h1, l0, l1);
    ((uint2*)h)[i] = make_uint2(h0, h1);
    ((uint2*)l)[i] = make_uint2(l0, l1);
}

// ---------------------------------------------------------------------------
// Gate MLP
// ---------------------------------------------------------------------------
__global__ void gate_kernel(const float* __restrict__ sm,
                            const float* __restrict__ g1w,
                            const float* __restrict__ g1b,
                            const float* __restrict__ g2w,
                            const float* __restrict__ g2b) {
    int idx = blockIdx.x * blockDim.x + threadIdx.x;
    if (idx >= TOK) return;
    float m = sm[idx];
    float acc = g2b[0];
#pragma unroll 8
    for (int j = 0; j < GH; ++j) {
        float h = fmaf(m, g1w[j], g1b[j]);
        h = fmaxf(h, 0.f);
        acc = fmaf(h, g2w[j], acc);
    }
    g_gate[idx] = 1.f / (1.f + __expf(-acc));
}

// ---------------------------------------------------------------------------
// HMMA split-bf16 GEMM (cp.async 2-stage): C = A @ B^T + bias
// Pre-split bf16 inputs. Block 128x128, BK=32, 8 warps (2x4), warp 64x32.
// SPLIT_OUT: write bf16 hi/lo (for qkv), else fp32.
// ---------------------------------------------------------------------------
#define GSTR 40            // 32 data + 8 pad bf16 (80B rows, conflict-free)
#define GTILE (128 * GSTR) // elems per array per stage
#define GEMM_SMEM (2 * 4 * GTILE * 2)  // bytes = 81920

template <bool SPLIT_OUT>
__global__ void __launch_bounds__(256, 2) gemm_mma(
    const __nv_bfloat16* __restrict__ Ah, const __nv_bfloat16* __restrict__ Al,
    const __nv_bfloat16* __restrict__ Bh, const __nv_bfloat16* __restrict__ Bl,
    const float* __restrict__ bias,
    float* __restrict__ Cout,
    __nv_bfloat16* __restrict__ Ch, __nv_bfloat16* __restrict__ Cl,
    int Nn, int K) {
    extern __shared__ __align__(16) __nv_bfloat16 smg[];
    uint32_t sb = smem_u32(smg);
    int tid = threadIdx.x, lane = tid & 31, wid = tid >> 5;
    int wm = wid >> 2, wn = wid & 3;
    int bm = blockIdx.y * 128, bn = blockIdx.x * 128;

    const __nv_bfloat16* gsrc[4] = {Ah, Al, Bh, Bl};

    auto load_stage = [&](int st, int k0) {
#pragma unroll
        for (int arr = 0; arr < 4; ++arr) {
            int r0 = (arr < 2) ? bm : bn;
            const __nv_bfloat16* g = gsrc[arr];
#pragma unroll
            for (int j = 0; j < 2; ++j) {
                int c = tid + j * 256;
                int row = c >> 2, co = (c & 3) * 8;
                cpa16(sb + ((st * 4 + arr) * GTILE + row * GSTR + co) * 2,
                      g + (size_t)(r0 + row) * K + k0 + co);
            }
        }
    };

    float acc[4][4][4] = {};
    const int nIt = K / 32;

    load_stage(0, 0);
    cpa_commit();

    for (int it = 0; it < nIt; ++it) {
        int st = it & 1;
        if (it + 1 < nIt) {
            load_stage(st ^ 1, (it + 1) * 32);
            cpa_commit();
            cpa_wait<1>();
        } else {
            cpa_wait<0>();
        }
        __syncthreads();

        uint32_t uAh = sb + (st * 4 + 0) * GTILE * 2;
        uint32_t uAl = sb + (st * 4 + 1) * GTILE * 2;
        uint32_t uBh = sb + (st * 4 + 2) * GTILE * 2;
        uint32_t uBl = sb + (st * 4 + 3) * GTILE * 2;
#pragma unroll
        for (int kk = 0; kk < 2; ++kk) {
            uint32_t cb = kk * 16 + (lane >> 4) * 8;
            uint32_t bh[2][4], bl[2][4];
#pragma unroll
            for (int bt = 0; bt < 2; ++bt) {
                uint32_t ro = (wn * 32 + bt * 16 + (lane & 15)) * GSTR + cb;
                ldsm4(bh[bt], uBh + 2 * ro);
                ldsm4(bl[bt], uBl + 2 * ro);
            }
#pragma unroll
            for (int mi = 0; mi < 4; ++mi) {
                uint32_t ro = (wm * 64 + mi * 16 + (lane & 15)) * GSTR + cb;
                uint32_t ah[4], al[4];
                ldsm4(ah, uAh + 2 * ro);
                ldsm4(al, uAl + 2 * ro);
#pragma unroll
                for (int bt = 0; bt < 2; ++bt) {
                    mma16816(acc[mi][2 * bt],     ah, bh[bt][0], bh[bt][2]);
                    mma16816(acc[mi][2 * bt],     ah, bl[bt][0], bl[bt][2]);
                    mma16816(acc[mi][2 * bt],     al, bh[bt][0], bh[bt][2]);
                    mma16816(acc[mi][2 * bt + 1], ah, bh[bt][1], bh[bt][3]);
                    mma16816(acc[mi][2 * bt + 1], ah, bl[bt][1], bl[bt][3]);
                    mma16816(acc[mi][2 * bt + 1], al, bh[bt][1], bh[bt][3]);
                }
            }
        }
        __syncthreads();
    }

    int r = lane >> 2, c2 = (lane & 3) * 2;
#pragma unroll
    for (int mi = 0; mi < 4; ++mi) {
        int row0 = bm + wm * 64 + mi * 16 + r;
#pragma unroll
        for (int ni = 0; ni < 4; ++ni) {
            int col = bn + wn * 32 + ni * 8 + c2;
            float bx = bias[col], by = bias[col + 1];
            float o00 = acc[mi][ni][0] + bx, o01 = acc[mi][ni][1] + by;
            float o10 = acc[mi][ni][2] + bx, o11 = acc[mi][ni][3] + by;
            if (SPLIT_OUT) {
                uint32_t hv, lv;
                pack2(o00, o01, hv, lv);
                *(uint32_t*)&Ch[(size_t)row0 * Nn + col] = hv;
                *(uint32_t*)&Cl[(size_t)row0 * Nn + col] = lv;
                pack2(o10, o11, hv, lv);
                *(uint32_t*)&Ch[(size_t)(row0 + 8) * Nn + col] = hv;
                *(uint32_t*)&Cl[(size_t)(row0 + 8) * Nn + col] = lv;
            } else {
                *(float2*)(Cout + (size_t)row0 * Nn + col) = make_float2(o00, o01);
                *(float2*)(Cout + (size_t)(row0 + 8) * Nn + col) = make_float2(o10, o11);
            }
        }
    }
}

// ---------------------------------------------------------------------------
// Flash attention, HMMA split-bf16, gated logits, cp.async 2-stage K/V.
// Block = (b,h) x 64-query tile, 4 warps. Inputs pre-split bf16 (g_qh/g_ql).
// ---------------------------------------------------------------------------
#define ASTR 72                 // 64 data + 8 pad bf16 (144B rows)
#define AQ (64 * ASTR)          // elems per Q array
#define ASSZ (4 * AQ + 128)     // stage: K h/l, V h/l + 64 floats gate
#define ATN_SMEM ((2 * AQ + 2 * ASSZ) * 2)  // bytes = 92672

__global__ void __launch_bounds__(128) attn_mma() {
    extern __shared__ __align__(16) __nv_bfloat16 sma[];
    uint32_t sb = smem_u32(sma);
    int tid = threadIdx.x, lane = tid & 31, wid = tid >> 5;
    int bhid = blockIdx.y;
    int b = bhid >> 4, h = bhid & 15;
    int q0 = blockIdx.x * 64;

    uint32_t uQh = sb;
    uint32_t uQl = sb + AQ * 2;

    // Prologue: Q tiles (hi/lo) via cp.async
#pragma unroll
    for (int j = 0; j < 4; ++j) {
        int c = tid + j * 128;
        int row = c >> 3, co = (c & 7) * 8;
        size_t gi = (size_t)(b * NN + q0 + row) * C3 + h * HD + co;
        cpa16(uQh + (row * ASTR + co) * 2, g_qh + gi);
        cpa16(uQl + (row * ASTR + co) * 2, g_ql + gi);
    }

    auto load_stage = [&](int st, int kt) {
        uint32_t base = sb + (2 * AQ + st * ASSZ) * 2;
#pragma unroll
        for (int j = 0; j < 4; ++j) {
            int c = tid + j * 128;
            int row = c >> 3, co = (c & 7) * 8;
            size_t gi = (size_t)(b * NN + kt + row) * C3 + h * HD + co;
            uint32_t so = (row * ASTR + co) * 2;
            cpa16(base + 0 * AQ * 2 + so, g_qh + gi + CC);       // K hi
            cpa16(base + 1 * AQ * 2 + so, g_ql + gi + CC);       // K lo
            cpa16(base + 2 * AQ * 2 + so, g_qh + gi + 2 * CC);   // V hi
            cpa16(base + 3 * AQ * 2 + so, g_ql + gi + 2 * CC);   // V lo
        }
        if (tid < 16)
            cpa16(base + 4 * AQ * 2 + tid * 16, g_gate + b * NN + kt + tid * 4);
    };

    load_stage(0, 0);
    cpa_commit();

    float m0 = -1e30f, m1 = -1e30f, l0s = 0.f, l1s = 0.f;
    float o[8][4] = {};

    for (int it = 0; it < NN / 64; ++it) {
        int st = it & 1;
        if (it + 1 < NN / 64) {
            load_stage(st ^ 1, (it + 1) * 64);
            cpa_commit();
            cpa_wait<1>();
        } else {
            cpa_wait<0>();
        }
        __syncthreads();

        uint32_t base = sb + (2 * AQ + st * ASSZ) * 2;
        uint32_t uKh = base, uKl = base + AQ * 2;
        uint32_t uVh = base + 2 * AQ * 2, uVl = base + 3 * AQ * 2;
        const float* gs = (const float*)(sma + (2 * AQ + st * ASSZ) + 4 * AQ);

        // ---- S = Q @ K^T ----
        float S[8][4] = {};
#pragma unroll
        for (int kk = 0; kk < 4; ++kk) {
            uint32_t cb = kk * 16 + (lane >> 4) * 8;
            uint32_t qro = (wid * 16 + (lane & 15)) * ASTR + cb;
            uint32_t qh[4], ql[4];
            ldsm4(qh, uQh + 2 * qro);
            ldsm4(ql, uQl + 2 * qro);
#pragma unroll
            for (int nt2 = 0; nt2 < 4; ++nt2) {
                uint32_t kro = (nt2 * 16 + (lane & 15)) * ASTR + cb;
                uint32_t kh[4], kl[4];
                ldsm4(kh, uKh + 2 * kro);
                ldsm4(kl, uKl + 2 * kro);
                mma16816(S[2 * nt2],     qh, kh[0], kh[2]);
                mma16816(S[2 * nt2],     qh, kl[0], kl[2]);
                mma16816(S[2 * nt2],     ql, kh[0], kh[2]);
                mma16816(S[2 * nt2 + 1], qh, kh[1], kh[3]);
                mma16816(S[2 * nt2 + 1], qh, kl[1], kl[3]);
                mma16816(S[2 * nt2 + 1], ql, kh[1], kh[3]);
            }
        }
        // ---- scale * gate[key] ----
        int kc = (lane & 3) * 2;
#pragma unroll
        for (int nt = 0; nt < 8; ++nt) {
            float ga = gs[nt * 8 + kc] * 0.125f;
            float gb = gs[nt * 8 + kc + 1] * 0.125f;
            S[nt][0] *= ga; S[nt][1] *= gb;
            S[nt][2] *= ga; S[nt][3] *= gb;
        }
        // ---- online softmax ----
        float mx0 = m0, mx1 = m1;
#pragma unroll
        for (int nt = 0; nt < 8; ++nt) {
            mx0 = fmaxf(mx0, fmaxf(S[nt][0], S[nt][1]));
            mx1 = fmaxf(mx1, fmaxf(S[nt][2], S[nt][3]));
        }
        mx0 = fmaxf(mx0, __shfl_xor_sync(0xffffffffu, mx0, 1));
        mx0 = fmaxf(mx0, __shfl_xor_sync(0xffffffffu, mx0, 2));
        mx1 = fmaxf(mx1, __shfl_xor_sync(0xffffffffu, mx1, 1));
        mx1 = fmaxf(mx1, __shfl_xor_sync(0xffffffffu, mx1, 2));
        float c0 = __expf(m0 - mx0), c1 = __expf(m1 - mx1);
        m0 = mx0; m1 = mx1;
        l0s *= c0; l1s *= c1;
#pragma unroll
        for (int dt = 0; dt < 8; ++dt) {
            o[dt][0] *= c0; o[dt][1] *= c0;
            o[dt][2] *= c1; o[dt][3] *= c1;
        }
        float s0 = 0.f, s1 = 0.f;
#pragma unroll
        for (int nt = 0; nt < 8; ++nt) {
            S[nt][0] = __expf(S[nt][0] - mx0); s0 += S[nt][0];
            S[nt][1] = __expf(S[nt][1] - mx0); s0 += S[nt][1];
            S[nt][2] = __expf(S[nt][2] - mx1); s1 += S[nt][2];
            S[nt][3] = __expf(S[nt][3] - mx1); s1 += S[nt][3];
        }
        s0 += __shfl_xor_sync(0xffffffffu, s0, 1);
        s0 += __shfl_xor_sync(0xffffffffu, s0, 2);
        s1 += __shfl_xor_sync(0xffffffffu, s1, 1);
        s1 += __shfl_xor_sync(0xffffffffu, s1, 2);
        l0s += s0; l1s += s1;
        // ---- P (C-frag) -> A-frag repack, split hi/lo ----
        uint32_t ph[4][4], pl[4][4];
#pragma unroll
        for (int kb = 0; kb < 4; ++kb) {
            pack2(S[2 * kb][0],     S[2 * kb][1],     ph[kb][0], pl[kb][0]);
            pack2(S[2 * kb][2],     S[2 * kb][3],     ph[kb][1], pl[kb][1]);
            pack2(S[2 * kb + 1][0], S[2 * kb + 1][1], ph[kb][2], pl[kb][2]);
            pack2(S[2 * kb + 1][2], S[2 * kb + 1][3], ph[kb][3], pl[kb][3]);
        }
        // ---- O += P @ V ----
#pragma unroll
        for (int kb = 0; kb < 4; ++kb) {
#pragma unroll
            for (int dt2 = 0; dt2 < 4; ++dt2) {
                uint32_t vro = (kb * 16 + (lane & 15)) * ASTR
                             + dt2 * 16 + (lane >> 4) * 8;
                uint32_t vh[4], vl[4];
                ldsm4t(vh, uVh + 2 * vro);
                ldsm4t(vl, uVl + 2 * vro);
                mma16816(o[2 * dt2],     ph[kb], vh[0], vh[1]);
                mma16816(o[2 * dt2],     ph[kb], vl[0], vl[1]);
                mma16816(o[2 * dt2],     pl[kb], vh[0], vh[1]);
                mma16816(o[2 * dt2 + 1], ph[kb], vh[2], vh[3]);
                mma16816(o[2 * dt2 + 1], ph[kb], vl[2], vl[3]);
                mma16816(o[2 * dt2 + 1], pl[kb], vh[2], vh[3]);
            }
        }
        __syncthreads();
    }

    // Epilogue: normalize, write bf16 hi/lo for proj GEMM
    float i0 = 1.f / l0s, i1 = 1.f / l1s;
    int r = lane >> 2, c2 = (lane & 3) * 2;
    int row0 = q0 + wid * 16 + r;
#pragma unroll
    for (int dt = 0; dt < 8; ++dt) {
        int d = dt * 8 + c2;
        uint32_t hv, lv;
        size_t gi0 = (size_t)(b * NN + row0) * CC + h * HD + d;
        size_t gi1 = (size_t)(b * NN + row0 + 8) * CC + h * HD + d;
        pack2(o[dt][0] * i0, o[dt][1] * i0, hv, lv);
        *(uint32_t*)&g_ath[gi0] = hv;
        *(uint32_t*)&g_atl[gi0] = lv;
        pack2(o[dt][2] * i1, o[dt][3] * i1, hv, lv);
        *(uint32_t*)&g_ath[gi1] = hv;
        *(uint32_t*)&g_atl[gi1] = lv;
    }
}

// ---------------------------------------------------------------------------
// Launch
// ---------------------------------------------------------------------------
extern "C" void kernel_launch(void* const* d_in, const int* in_sizes, int n_in,
                              void* d_out, int out_size) {
    (void)in_sizes; (void)n_in; (void)out_size;
    const float* x      = (const float*)d_in[0];
    const float* smask  = (const float*)d_in[1];
    const float* qkv_w  = (const float*)d_in[2];
    const float* qkv_b  = (const float*)d_in[3];
    const float* proj_w = (const float*)d_in[4];
    const float* proj_b = (const float*)d_in[5];
    const float* g1_w   = (const float*)d_in[6];
    const float* g1_b   = (const float*)d_in[7];
    const float* g2_w   = (const float*)d_in[8];
    const float* g2_b   = (const float*)d_in[9];
    float* out = (float*)d_out;

    __nv_bfloat16 *xh, *xl, *wqh, *wql, *wph, *wpl, *qh, *ql, *ath, *atl;
    cudaGetSymbolAddress((void**)&xh,  g_xh);  cudaGetSymbolAddress((void**)&xl,  g_xl);
    cudaGetSymbolAddress((void**)&wqh, g_wqh); cudaGetSymbolAddress((void**)&wql, g_wql);
    cudaGetSymbolAddress((void**)&wph, g_wph); cudaGetSymbolAddress((void**)&wpl, g_wpl);
    cudaGetSymbolAddress((void**)&qh,  g_qh);  cudaGetSymbolAddress((void**)&ql,  g_ql);
    cudaGetSymbolAddress((void**)&ath, g_ath); cudaGetSymbolAddress((void**)&atl, g_atl);

    // 0. pre-split inputs to bf16 hi/lo
    split_kernel<<<(TOK * CC / 4 + 255) / 256, 256>>>(x, xh, xl, TOK * CC / 4);
    split_kernel<<<(C3 * CC / 4 + 255) / 256, 256>>>(qkv_w, wqh, wql, C3 * CC / 4);
    split_kernel<<<(CC * CC / 4 + 255) / 256, 256>>>(proj_w, wph, wpl, CC * CC / 4);

    // 1. gate
    gate_kernel<<<(TOK + 255) / 256, 256>>>(smask, g1_w, g1_b, g2_w, g2_b);

    // 2. qkv = x @ qkv_w^T + qkv_b  (bf16 hi/lo out)
    cudaFuncSetAttribute(gemm_mma<true>,
                         cudaFuncAttributeMaxDynamicSharedMemorySize, GEMM_SMEM);
    gemm_mma<true><<<dim3(C3 / 128, TOK / 128), 256, GEMM_SMEM>>>(
        xh, xl, wqh, wql, qkv_b, nullptr, qh, ql, C3, CC);

    // 3. attention
    cudaFuncSetAttribute(attn_mma,
                         cudaFuncAttributeMaxDynamicSharedMemorySize, ATN_SMEM);
    attn_mma<<<dim3(NN / 64, BB * HH), 128, ATN_SMEM>>>();

    // 4. out = att @ proj_w^T + proj_b  (fp32 out)
    cudaFuncSetAttribute(gemm_mma<false>,
                         cudaFuncAttributeMaxDynamicSharedMemorySize, GEMM_SMEM);
    gemm_mma<false><<<dim3(CC / 128, TOK / 128), 256, GEMM_SMEM>>>(
        ath, atl, wph, wpl, proj_b, out, nullptr, nullptr, CC, CC);
}

// round 6
// speedup vs baseline: 1.0013x; 1.0013x over previous
#include <cuda_runtime.h>
#include <cuda_bf16.h>
#include <cstdint>
#include <math.h>

// Problem constants
#define BB 2
#define NN 2048
#define CC 1024
#define HH 16
#define HD 64
#define GH 256
#define C3 3072
#define TOK (BB*NN)   // 4096

// Scratch (device globals: allocation-free). bf16 hi/lo split everywhere.
__device__ __nv_bfloat16 g_xh[(size_t)TOK * CC],  g_xl[(size_t)TOK * CC];
__device__ __nv_bfloat16 g_wqh[(size_t)C3 * CC],  g_wql[(size_t)C3 * CC];
__device__ __nv_bfloat16 g_wph[(size_t)CC * CC],  g_wpl[(size_t)CC * CC];
__device__ __nv_bfloat16 g_qh[(size_t)TOK * C3],  g_ql[(size_t)TOK * C3];
__device__ __nv_bfloat16 g_ath[(size_t)TOK * CC], g_atl[(size_t)TOK * CC];
__device__ float g_gate[TOK];

// ---------------------------------------------------------------------------
// Helpers (baseline PTX: ldmatrix sm_75, mma.sync bf16 sm_80, cp.async sm_80)
// ---------------------------------------------------------------------------
__device__ __forceinline__ uint32_t smem_u32(const void* p) {
    uint32_t a;
    asm("{ .reg .u64 t; cvta.to.shared.u64 t, %1; cvt.u32.u64 %0, t; }"
        : "=r"(a) : "l"(p));
    return a;
}
__device__ __forceinline__ void ldsm4(uint32_t* r, uint32_t addr) {
    asm volatile("ldmatrix.sync.aligned.m8n8.x4.shared.b16 {%0,%1,%2,%3}, [%4];"
                 : "=r"(r[0]), "=r"(r[1]), "=r"(r[2]), "=r"(r[3]) : "r"(addr));
}
__device__ __forceinline__ void ldsm4t(uint32_t* r, uint32_t addr) {
    asm volatile("ldmatrix.sync.aligned.m8n8.x4.trans.shared.b16 {%0,%1,%2,%3}, [%4];"
                 : "=r"(r[0]), "=r"(r[1]), "=r"(r[2]), "=r"(r[3]) : "r"(addr));
}
__device__ __forceinline__ void mma16816(float* d, const uint32_t* a,
                                         uint32_t b0, uint32_t b1) {
    asm volatile(
        "mma.sync.aligned.m16n8k16.row.col.f32.bf16.bf16.f32 "
        "{%0,%1,%2,%3}, {%4,%5,%6,%7}, {%8,%9}, {%0,%1,%2,%3};"
        : "+f"(d[0]), "+f"(d[1]), "+f"(d[2]), "+f"(d[3])
        : "r"(a[0]), "r"(a[1]), "r"(a[2]), "r"(a[3]), "r"(b0), "r"(b1));
}
__device__ __forceinline__ void cpa16(uint32_t dst, const void* src) {
    asm volatile("cp.async.cg.shared.global [%0], [%1], 16;"
                 :: "r"(dst), "l"(src) : "memory");
}
__device__ __forceinline__ void cpa_commit() {
    asm volatile("cp.async.commit_group;" ::: "memory");
}
template <int N>
__device__ __forceinline__ void cpa_wait() {
    asm volatile("cp.async.wait_group %0;" :: "n"(N) : "memory");
}
// Split (x,y) fp32 pair into bf16x2 hi + bf16x2 lo
__device__ __forceinline__ void pack2(float x, float y, uint32_t& hi, uint32_t& lo) {
    __nv_bfloat162 h = __floats2bfloat162_rn(x, y);
    float2 hf = __bfloat1622float2(h);
    __nv_bfloat162 l = __floats2bfloat162_rn(x - hf.x, y - hf.y);
    hi = *reinterpret_cast<uint32_t*>(&h);
    lo = *reinterpret_cast<uint32_t*>(&l);
}
__device__ __forceinline__ void split4(float4 v, uint32_t& h0, uint32_t& h1,
                                       uint32_t& l0, uint32_t& l1) {
    pack2(v.x, v.y, h0, l0);
    pack2(v.z, v.w, h1, l1);
}

// ---------------------------------------------------------------------------
// Pre-split: fp32 -> bf16 hi/lo
// ---------------------------------------------------------------------------
__global__ void split_kernel(const float* __restrict__ s,
                             __nv_bfloat16* __restrict__ h,
                             __nv_bfloat16* __restrict__ l, int n4) {
    int i = blockIdx.x * blockDim.x + threadIdx.x;
    if (i >= n4) return;
    float4 v = ((const float4*)s)[i];
    uint32_t h0, h1, l0, l1;
    split4(v, h0, h1, l0, l1);
    ((uint2*)h)[i] = make_uint2(h0, h1);
    ((uint2*)l)[i] = make_uint2(l0, l1);
}

// ---------------------------------------------------------------------------
// Gate MLP: one warp per token, lanes split GH, shuffle-reduce.
// ---------------------------------------------------------------------------
__global__ void gate_kernel(const float* __restrict__ sm,
                            const float* __restrict__ g1w,
                            const float* __restrict__ g1b,
                            const float* __restrict__ g2w,
                            const float* __restrict__ g2b) {
    int w = (blockIdx.x * blockDim.x + threadIdx.x) >> 5;
    int lane = threadIdx.x & 31;
    if (w >= TOK) return;
    float m = sm[w];
    float acc = 0.f;
#pragma unroll
    for (int j = lane; j < GH; j += 32) {
        float h = fmaxf(fmaf(m, g1w[j], g1b[j]), 0.f);
        acc = fmaf(h, g2w[j], acc);
    }
#pragma unroll
    for (int o = 16; o; o >>= 1) acc += __shfl_xor_sync(0xffffffffu, acc, o);
    if (lane == 0) g_gate[w] = 1.f / (1.f + __expf(-(acc + g2b[0])));
}

// ---------------------------------------------------------------------------
// HMMA split-bf16 GEMM (cp.async 2-stage): C = A @ B^T + bias
// Pre-split bf16 inputs. Block 128x128, BK=32, 8 warps (2x4), warp 64x32.
// ---------------------------------------------------------------------------
#define GSTR 40            // 32 data + 8 pad bf16 (80B rows, conflict-free)
#define GTILE (128 * GSTR) // elems per array per stage
#define GEMM_SMEM (2 * 4 * GTILE * 2)  // bytes = 81920

template <bool SPLIT_OUT>
__global__ void __launch_bounds__(256, 2) gemm_mma(
    const __nv_bfloat16* __restrict__ Ah, const __nv_bfloat16* __restrict__ Al,
    const __nv_bfloat16* __restrict__ Bh, const __nv_bfloat16* __restrict__ Bl,
    const float* __restrict__ bias,
    float* __restrict__ Cout,
    __nv_bfloat16* __restrict__ Ch, __nv_bfloat16* __restrict__ Cl,
    int Nn, int K) {
    extern __shared__ __align__(16) __nv_bfloat16 smg[];
    uint32_t sb = smem_u32(smg);
    int tid = threadIdx.x, lane = tid & 31, wid = tid >> 5;
    int wm = wid >> 2, wn = wid & 3;
    int bm = blockIdx.y * 128, bn = blockIdx.x * 128;

    const __nv_bfloat16* gsrc[4] = {Ah, Al, Bh, Bl};

    auto load_stage = [&](int st, int k0) {
#pragma unroll
        for (int arr = 0; arr < 4; ++arr) {
            int r0 = (arr < 2) ? bm : bn;
            const __nv_bfloat16* g = gsrc[arr];
#pragma unroll
            for (int j = 0; j < 2; ++j) {
                int c = tid + j * 256;
                int row = c >> 2, co = (c & 3) * 8;
                cpa16(sb + ((st * 4 + arr) * GTILE + row * GSTR + co) * 2,
                      g + (size_t)(r0 + row) * K + k0 + co);
            }
        }
    };

    float acc[4][4][4] = {};
    const int nIt = K / 32;

    load_stage(0, 0);
    cpa_commit();

    for (int it = 0; it < nIt; ++it) {
        int st = it & 1;
        if (it + 1 < nIt) {
            load_stage(st ^ 1, (it + 1) * 32);
            cpa_commit();
            cpa_wait<1>();
        } else {
            cpa_wait<0>();
        }
        __syncthreads();

        uint32_t uAh = sb + (st * 4 + 0) * GTILE * 2;
        uint32_t uAl = sb + (st * 4 + 1) * GTILE * 2;
        uint32_t uBh = sb + (st * 4 + 2) * GTILE * 2;
        uint32_t uBl = sb + (st * 4 + 3) * GTILE * 2;
#pragma unroll
        for (int kk = 0; kk < 2; ++kk) {
            uint32_t cb = kk * 16 + (lane >> 4) * 8;
            uint32_t bh[2][4], bl[2][4];
#pragma unroll
            for (int bt = 0; bt < 2; ++bt) {
                uint32_t ro = (wn * 32 + bt * 16 + (lane & 15)) * GSTR + cb;
                ldsm4(bh[bt], uBh + 2 * ro);
                ldsm4(bl[bt], uBl + 2 * ro);
            }
#pragma unroll
            for (int mi = 0; mi < 4; ++mi) {
                uint32_t ro = (wm * 64 + mi * 16 + (lane & 15)) * GSTR + cb;
                uint32_t ah[4], al[4];
                ldsm4(ah, uAh + 2 * ro);
                ldsm4(al, uAl + 2 * ro);
#pragma unroll
                for (int bt = 0; bt < 2; ++bt) {
                    mma16816(acc[mi][2 * bt],     ah, bh[bt][0], bh[bt][2]);
                    mma16816(acc[mi][2 * bt],     ah, bl[bt][0], bl[bt][2]);
                    mma16816(acc[mi][2 * bt],     al, bh[bt][0], bh[bt][2]);
                    mma16816(acc[mi][2 * bt + 1], ah, bh[bt][1], bh[bt][3]);
                    mma16816(acc[mi][2 * bt + 1], ah, bl[bt][1], bl[bt][3]);
                    mma16816(acc[mi][2 * bt + 1], al, bh[bt][1], bh[bt][3]);
                }
            }
        }
        __syncthreads();
    }

    int r = lane >> 2, c2 = (lane & 3) * 2;
#pragma unroll
    for (int mi = 0; mi < 4; ++mi) {
        int row0 = bm + wm * 64 + mi * 16 + r;
#pragma unroll
        for (int ni = 0; ni < 4; ++ni) {
            int col = bn + wn * 32 + ni * 8 + c2;
            float bx = bias[col], by = bias[col + 1];
            float o00 = acc[mi][ni][0] + bx, o01 = acc[mi][ni][1] + by;
            float o10 = acc[mi][ni][2] + bx, o11 = acc[mi][ni][3] + by;
            if (SPLIT_OUT) {
                uint32_t hv, lv;
                pack2(o00, o01, hv, lv);
                *(uint32_t*)&Ch[(size_t)row0 * Nn + col] = hv;
                *(uint32_t*)&Cl[(size_t)row0 * Nn + col] = lv;
                pack2(o10, o11, hv, lv);
                *(uint32_t*)&Ch[(size_t)(row0 + 8) * Nn + col] = hv;
                *(uint32_t*)&Cl[(size_t)(row0 + 8) * Nn + col] = lv;
            } else {
                *(float2*)(Cout + (size_t)row0 * Nn + col) = make_float2(o00, o01);
                *(float2*)(Cout + (size_t)(row0 + 8) * Nn + col) = make_float2(o10, o11);
            }
        }
    }
}

// ---------------------------------------------------------------------------
// Flash attention, HMMA split-bf16, gated logits, cp.async 2-stage K/V.
// Q fragments hoisted into registers for the whole key loop.
// ---------------------------------------------------------------------------
#define ASTR 72                 // 64 data + 8 pad bf16 (144B rows)
#define AQ (64 * ASTR)          // elems per Q array
#define ASSZ (4 * AQ + 128)     // stage: K h/l, V h/l + 64 floats gate
#define ATN_SMEM ((2 * AQ + 2 * ASSZ) * 2)  // bytes = 92672

__global__ void __launch_bounds__(128, 2) attn_mma() {
    extern __shared__ __align__(16) __nv_bfloat16 sma[];
    uint32_t sb = smem_u32(sma);
    int tid = threadIdx.x, lane = tid & 31, wid = tid >> 5;
    int bhid = blockIdx.y;
    int b = bhid >> 4, h = bhid & 15;
    int q0 = blockIdx.x * 64;

    uint32_t uQh = sb;
    uint32_t uQl = sb + AQ * 2;

    // Prologue: Q tiles (hi/lo) via cp.async — own commit group
#pragma unroll
    for (int j = 0; j < 4; ++j) {
        int c = tid + j * 128;
        int row = c >> 3, co = (c & 7) * 8;
        size_t gi = (size_t)(b * NN + q0 + row) * C3 + h * HD + co;
        cpa16(uQh + (row * ASTR + co) * 2, g_qh + gi);
        cpa16(uQl + (row * ASTR + co) * 2, g_ql + gi);
    }
    cpa_commit();

    auto load_stage = [&](int st, int kt) {
        uint32_t base = sb + (2 * AQ + st * ASSZ) * 2;
#pragma unroll
        for (int j = 0; j < 4; ++j) {
            int c = tid + j * 128;
            int row = c >> 3, co = (c & 7) * 8;
            size_t gi = (size_t)(b * NN + kt + row) * C3 + h * HD + co;
            uint32_t so = (row * ASTR + co) * 2;
            cpa16(base + 0 * AQ * 2 + so, g_qh + gi + CC);       // K hi
            cpa16(base + 1 * AQ * 2 + so, g_ql + gi + CC);       // K lo
            cpa16(base + 2 * AQ * 2 + so, g_qh + gi + 2 * CC);   // V hi
            cpa16(base + 3 * AQ * 2 + so, g_ql + gi + 2 * CC);   // V lo
        }
        if (tid < 16)
            cpa16(base + 4 * AQ * 2 + tid * 16, g_gate + b * NN + kt + tid * 4);
    };

    load_stage(0, 0);
    cpa_commit();

    // Hoist Q fragments: wait on the Q group (1 group may stay pending),
    // then ldmatrix once into registers.
    uint32_t qfh[4][4], qfl[4][4];
    cpa_wait<1>();
    __syncthreads();
#pragma unroll
    for (int kk = 0; kk < 4; ++kk) {
        uint32_t cb = kk * 16 + (lane >> 4) * 8;
        uint32_t qro = (wid * 16 + (lane & 15)) * ASTR + cb;
        ldsm4(qfh[kk], uQh + 2 * qro);
        ldsm4(qfl[kk], uQl + 2 * qro);
    }

    float m0 = -1e30f, m1 = -1e30f, l0s = 0.f, l1s = 0.f;
    float o[8][4] = {};

    for (int it = 0; it < NN / 64; ++it) {
        int st = it & 1;
        if (it + 1 < NN / 64) {
            load_stage(st ^ 1, (it + 1) * 64);
            cpa_commit();
            cpa_wait<1>();
        } else {
            cpa_wait<0>();
        }
        __syncthreads();

        uint32_t base = sb + (2 * AQ + st * ASSZ) * 2;
        uint32_t uKh = base, uKl = base + AQ * 2;
        uint32_t uVh = base + 2 * AQ * 2, uVl = base + 3 * AQ * 2;
        const float* gs = (const float*)(sma + (2 * AQ + st * ASSZ) + 4 * AQ);

        // ---- S = Q @ K^T (Q frags in registers) ----
        float S[8][4] = {};
#pragma unroll
        for (int kk = 0; kk < 4; ++kk) {
            uint32_t cb = kk * 16 + (lane >> 4) * 8;
#pragma unroll
            for (int nt2 = 0; nt2 < 4; ++nt2) {
                uint32_t kro = (nt2 * 16 + (lane & 15)) * ASTR + cb;
                uint32_t kh[4], kl[4];
                ldsm4(kh, uKh + 2 * kro);
                ldsm4(kl, uKl + 2 * kro);
                mma16816(S[2 * nt2],     qfh[kk], kh[0], kh[2]);
                mma16816(S[2 * nt2],     qfh[kk], kl[0], kl[2]);
                mma16816(S[2 * nt2],     qfl[kk], kh[0], kh[2]);
                mma16816(S[2 * nt2 + 1], qfh[kk], kh[1], kh[3]);
                mma16816(S[2 * nt2 + 1], qfh[kk], kl[1], kl[3]);
                mma16816(S[2 * nt2 + 1], qfl[kk], kh[1], kh[3]);
            }
        }
        // ---- scale * gate[key] ----
        int kc = (lane & 3) * 2;
#pragma unroll
        for (int nt = 0; nt < 8; ++nt) {
            float ga = gs[nt * 8 + kc] * 0.125f;
            float gb = gs[nt * 8 + kc + 1] * 0.125f;
            S[nt][0] *= ga; S[nt][1] *= gb;
            S[nt][2] *= ga; S[nt][3] *= gb;
        }
        // ---- online softmax ----
        float mx0 = m0, mx1 = m1;
#pragma unroll
        for (int nt = 0; nt < 8; ++nt) {
            mx0 = fmaxf(mx0, fmaxf(S[nt][0], S[nt][1]));
            mx1 = fmaxf(mx1, fmaxf(S[nt][2], S[nt][3]));
        }
        mx0 = fmaxf(mx0, __shfl_xor_sync(0xffffffffu, mx0, 1));
        mx0 = fmaxf(mx0, __shfl_xor_sync(0xffffffffu, mx0, 2));
        mx1 = fmaxf(mx1, __shfl_xor_sync(0xffffffffu, mx1, 1));
        mx1 = fmaxf(mx1, __shfl_xor_sync(0xffffffffu, mx1, 2));
        float c0 = __expf(m0 - mx0), c1 = __expf(m1 - mx1);
        m0 = mx0; m1 = mx1;
        l0s *= c0; l1s *= c1;
#pragma unroll
        for (int dt = 0; dt < 8; ++dt) {
            o[dt][0] *= c0; o[dt][1] *= c0;
            o[dt][2] *= c1; o[dt][3] *= c1;
        }
        float s0 = 0.f, s1 = 0.f;
#pragma unroll
        for (int nt = 0; nt < 8; ++nt) {
            S[nt][0] = __expf(S[nt][0] - mx0); s0 += S[nt][0];
            S[nt][1] = __expf(S[nt][1] - mx0); s0 += S[nt][1];
            S[nt][2] = __expf(S[nt][2] - mx1); s1 += S[nt][2];
            S[nt][3] = __expf(S[nt][3] - mx1); s1 += S[nt][3];
        }
        s0 += __shfl_xor_sync(0xffffffffu, s0, 1);
        s0 += __shfl_xor_sync(0xffffffffu, s0, 2);
        s1 += __shfl_xor_sync(0xffffffffu, s1, 1);
        s1 += __shfl_xor_sync(0xffffffffu, s1, 2);
        l0s += s0; l1s += s1;
        // ---- P (C-frag) -> A-frag repack, split hi/lo ----
        uint32_t ph[4][4], pl[4][4];
#pragma unroll
        for (int kb = 0; kb < 4; ++kb) {
            pack2(S[2 * kb][0],     S[2 * kb][1],     ph[kb][0], pl[kb][0]);
            pack2(S[2 * kb][2],     S[2 * kb][3],     ph[kb][1], pl[kb][1]);
            pack2(S[2 * kb + 1][0], S[2 * kb + 1][1], ph[kb][2], pl[kb][2]);
            pack2(S[2 * kb + 1][2], S[2 * kb + 1][3], ph[kb][3], pl[kb][3]);
        }
        // ---- O += P @ V ----
#pragma unroll
        for (int kb = 0; kb < 4; ++kb) {
#pragma unroll
            for (int dt2 = 0; dt2 < 4; ++dt2) {
                uint32_t vro = (kb * 16 + (lane & 15)) * ASTR
                             + dt2 * 16 + (lane >> 4) * 8;
                uint32_t vh[4], vl[4];
                ldsm4t(vh, uVh + 2 * vro);
                ldsm4t(vl, uVl + 2 * vro);
                mma16816(o[2 * dt2],     ph[kb], vh[0], vh[1]);
                mma16816(o[2 * dt2],     ph[kb], vl[0], vl[1]);
                mma16816(o[2 * dt2],     pl[kb], vh[0], vh[1]);
                mma16816(o[2 * dt2 + 1], ph[kb], vh[2], vh[3]);
                mma16816(o[2 * dt2 + 1], ph[kb], vl[2], vl[3]);
                mma16816(o[2 * dt2 + 1], pl[kb], vh[2], vh[3]);
            }
        }
        __syncthreads();
    }

    // Epilogue: normalize, write bf16 hi/lo for proj GEMM
    float i0 = 1.f / l0s, i1 = 1.f / l1s;
    int r = lane >> 2, c2 = (lane & 3) * 2;
    int row0 = q0 + wid * 16 + r;
#pragma unroll
    for (int dt = 0; dt < 8; ++dt) {
        int d = dt * 8 + c2;
        uint32_t hv, lv;
        size_t gi0 = (size_t)(b * NN + row0) * CC + h * HD + d;
        size_t gi1 = (size_t)(b * NN + row0 + 8) * CC + h * HD + d;
        pack2(o[dt][0] * i0, o[dt][1] * i0, hv, lv);
        *(uint32_t*)&g_ath[gi0] = hv;
        *(uint32_t*)&g_atl[gi0] = lv;
        pack2(o[dt][2] * i1, o[dt][3] * i1, hv, lv);
        *(uint32_t*)&g_ath[gi1] = hv;
        *(uint32_t*)&g_atl[gi1] = lv;
    }
}

// ---------------------------------------------------------------------------
// Launch
// ---------------------------------------------------------------------------
extern "C" void kernel_launch(void* const* d_in, const int* in_sizes, int n_in,
                              void* d_out, int out_size) {
    (void)in_sizes; (void)n_in; (void)out_size;
    const float* x      = (const float*)d_in[0];
    const float* smask  = (const float*)d_in[1];
    const float* qkv_w  = (const float*)d_in[2];
    const float* qkv_b  = (const float*)d_in[3];
    const float* proj_w = (const float*)d_in[4];
    const float* proj_b = (const float*)d_in[5];
    const float* g1_w   = (const float*)d_in[6];
    const float* g1_b   = (const float*)d_in[7];
    const float* g2_w   = (const float*)d_in[8];
    const float* g2_b   = (const float*)d_in[9];
    float* out = (float*)d_out;

    __nv_bfloat16 *xh, *xl, *wqh, *wql, *wph, *wpl, *qh, *ql, *ath, *atl;
    cudaGetSymbolAddress((void**)&xh,  g_xh);  cudaGetSymbolAddress((void**)&xl,  g_xl);
    cudaGetSymbolAddress((void**)&wqh, g_wqh); cudaGetSymbolAddress((void**)&wql, g_wql);
    cudaGetSymbolAddress((void**)&wph, g_wph); cudaGetSymbolAddress((void**)&wpl, g_wpl);
    cudaGetSymbolAddress((void**)&qh,  g_qh);  cudaGetSymbolAddress((void**)&ql,  g_ql);
    cudaGetSymbolAddress((void**)&ath, g_ath); cudaGetSymbolAddress((void**)&atl, g_atl);

    // 0. pre-split inputs to bf16 hi/lo
    split_kernel<<<(TOK * CC / 4 + 255) / 256, 256>>>(x, xh, xl, TOK * CC / 4);
    split_kernel<<<(C3 * CC / 4 + 255) / 256, 256>>>(qkv_w, wqh, wql, C3 * CC / 4);
    split_kernel<<<(CC * CC / 4 + 255) / 256, 256>>>(proj_w, wph, wpl, CC * CC / 4);

    // 1. gate (warp per token)
    gate_kernel<<<(TOK * 32 + 255) / 256, 256>>>(smask, g1_w, g1_b, g2_w, g2_b);

    // 2. qkv = x @ qkv_w^T + qkv_b  (bf16 hi/lo out)
    cudaFuncSetAttribute(gemm_mma<true>,
                         cudaFuncAttributeMaxDynamicSharedMemorySize, GEMM_SMEM);
    gemm_mma<true><<<dim3(C3 / 128, TOK / 128), 256, GEMM_SMEM>>>(
        xh, xl, wqh, wql, qkv_b, nullptr, qh, ql, C3, CC);

    // 3. attention
    cudaFuncSetAttribute(attn_mma,
                         cudaFuncAttributeMaxDynamicSharedMemorySize, ATN_SMEM);
    attn_mma<<<dim3(NN / 64, BB * HH), 128, ATN_SMEM>>>();

    // 4. out = att @ proj_w^T + proj_b  (fp32 out)
    cudaFuncSetAttribute(gemm_mma<false>,
                         cudaFuncAttributeMaxDynamicSharedMemorySize, GEMM_SMEM);
    gemm_mma<false><<<dim3(CC / 128, TOK / 128), 256, GEMM_SMEM>>>(
        ath, atl, wph, wpl, proj_b, out, nullptr, nullptr, CC, CC);
}

// round 7
// speedup vs baseline: 1.0105x; 1.0091x over previous
#include <cuda_runtime.h>
#include <cuda_bf16.h>
#include <cstdint>
#include <math.h>

// Problem constants
#define BB 2
#define NN 2048
#define CC 1024
#define HH 16
#define HD 64
#define GH 256
#define C3 3072
#define TOK (BB*NN)   // 4096

// Scratch (device globals: allocation-free). bf16 hi/lo split everywhere.
__device__ __nv_bfloat16 g_xh[(size_t)TOK * CC],  g_xl[(size_t)TOK * CC];
__device__ __nv_bfloat16 g_wqh[(size_t)C3 * CC],  g_wql[(size_t)C3 * CC];
__device__ __nv_bfloat16 g_wph[(size_t)CC * CC],  g_wpl[(size_t)CC * CC];
__device__ __nv_bfloat16 g_qh[(size_t)TOK * C3],  g_ql[(size_t)TOK * C3];
__device__ __nv_bfloat16 g_ath[(size_t)TOK * CC], g_atl[(size_t)TOK * CC];
__device__ float g_gate[TOK];

// ---------------------------------------------------------------------------
// Helpers
// ---------------------------------------------------------------------------
__device__ __forceinline__ uint32_t smem_u32(const void* p) {
    uint32_t a;
    asm("{ .reg .u64 t; cvta.to.shared.u64 t, %1; cvt.u32.u64 %0, t; }"
        : "=r"(a) : "l"(p));
    return a;
}
__device__ __forceinline__ void ldsm4(uint32_t* r, uint32_t addr) {
    asm volatile("ldmatrix.sync.aligned.m8n8.x4.shared.b16 {%0,%1,%2,%3}, [%4];"
                 : "=r"(r[0]), "=r"(r[1]), "=r"(r[2]), "=r"(r[3]) : "r"(addr));
}
__device__ __forceinline__ void ldsm4t(uint32_t* r, uint32_t addr) {
    asm volatile("ldmatrix.sync.aligned.m8n8.x4.trans.shared.b16 {%0,%1,%2,%3}, [%4];"
                 : "=r"(r[0]), "=r"(r[1]), "=r"(r[2]), "=r"(r[3]) : "r"(addr));
}
// NOTE: non-volatile — pure register dataflow, let ptxas schedule.
__device__ __forceinline__ void mma16816(float* d, const uint32_t* a,
                                         uint32_t b0, uint32_t b1) {
    asm("mma.sync.aligned.m16n8k16.row.col.f32.bf16.bf16.f32 "
        "{%0,%1,%2,%3}, {%4,%5,%6,%7}, {%8,%9}, {%0,%1,%2,%3};"
        : "+f"(d[0]), "+f"(d[1]), "+f"(d[2]), "+f"(d[3])
        : "r"(a[0]), "r"(a[1]), "r"(a[2]), "r"(a[3]), "r"(b0), "r"(b1));
}
__device__ __forceinline__ void cpa16(uint32_t dst, const void* src) {
    asm volatile("cp.async.cg.shared.global [%0], [%1], 16;"
                 :: "r"(dst), "l"(src) : "memory");
}
__device__ __forceinline__ void cpa_commit() {
    asm volatile("cp.async.commit_group;" ::: "memory");
}
template <int N>
__device__ __forceinline__ void cpa_wait() {
    asm volatile("cp.async.wait_group %0;" :: "n"(N) : "memory");
}
__device__ __forceinline__ void pack2(float x, float y, uint32_t& hi, uint32_t& lo) {
    __nv_bfloat162 h = __floats2bfloat162_rn(x, y);
    float2 hf = __bfloat1622float2(h);
    __nv_bfloat162 l = __floats2bfloat162_rn(x - hf.x, y - hf.y);
    hi = *reinterpret_cast<uint32_t*>(&h);
    lo = *reinterpret_cast<uint32_t*>(&l);
}
__device__ __forceinline__ void split4(float4 v, uint32_t& h0, uint32_t& h1,
                                       uint32_t& l0, uint32_t& l1) {
    pack2(v.x, v.y, h0, l0);
    pack2(v.z, v.w, h1, l1);
}

// ---------------------------------------------------------------------------
// Pre-split: fp32 -> bf16 hi/lo
// ---------------------------------------------------------------------------
__global__ void split_kernel(const float* __restrict__ s,
                             __nv_bfloat16* __restrict__ h,
                             __nv_bfloat16* __restrict__ l, int n4) {
    int i = blockIdx.x * blockDim.x + threadIdx.x;
    if (i >= n4) return;
    float4 v = ((const float4*)s)[i];
    uint32_t h0, h1, l0, l1;
    split4(v, h0, h1, l0, l1);
    ((uint2*)h)[i] = make_uint2(h0, h1);
    ((uint2*)l)[i] = make_uint2(l0, l1);
}

// ---------------------------------------------------------------------------
// Gate MLP: one warp per token
// ---------------------------------------------------------------------------
__global__ void gate_kernel(const float* __restrict__ sm,
                            const float* __restrict__ g1w,
                            const float* __restrict__ g1b,
                            const float* __restrict__ g2w,
                            const float* __restrict__ g2b) {
    int w = (blockIdx.x * blockDim.x + threadIdx.x) >> 5;
    int lane = threadIdx.x & 31;
    if (w >= TOK) return;
    float m = sm[w];
    float acc = 0.f;
#pragma unroll
    for (int j = lane; j < GH; j += 32) {
        float h = fmaxf(fmaf(m, g1w[j], g1b[j]), 0.f);
        acc = fmaf(h, g2w[j], acc);
    }
#pragma unroll
    for (int o = 16; o; o >>= 1) acc += __shfl_xor_sync(0xffffffffu, acc, o);
    if (lane == 0) g_gate[w] = 1.f / (1.f + __expf(-(acc + g2b[0])));
}

// ---------------------------------------------------------------------------
// HMMA split-bf16 GEMM (cp.async 2-stage): C = A @ B^T + bias
// Term-pass issue order: 8 independent acc chains between reuses.
// ---------------------------------------------------------------------------
#define GSTR 40
#define GTILE (128 * GSTR)
#define GEMM_SMEM (2 * 4 * GTILE * 2)

template <bool SPLIT_OUT>
__global__ void __launch_bounds__(256, 2) gemm_mma(
    const __nv_bfloat16* __restrict__ Ah, const __nv_bfloat16* __restrict__ Al,
    const __nv_bfloat16* __restrict__ Bh, const __nv_bfloat16* __restrict__ Bl,
    const float* __restrict__ bias,
    float* __restrict__ Cout,
    __nv_bfloat16* __restrict__ Ch, __nv_bfloat16* __restrict__ Cl,
    int Nn, int K) {
    extern __shared__ __align__(16) __nv_bfloat16 smg[];
    uint32_t sb = smem_u32(smg);
    int tid = threadIdx.x, lane = tid & 31, wid = tid >> 5;
    int wm = wid >> 2, wn = wid & 3;
    int bm = blockIdx.y * 128, bn = blockIdx.x * 128;

    const __nv_bfloat16* gsrc[4] = {Ah, Al, Bh, Bl};

    auto load_stage = [&](int st, int k0) {
#pragma unroll
        for (int arr = 0; arr < 4; ++arr) {
            int r0 = (arr < 2) ? bm : bn;
            const __nv_bfloat16* g = gsrc[arr];
#pragma unroll
            for (int j = 0; j < 2; ++j) {
                int c = tid + j * 256;
                int row = c >> 2, co = (c & 3) * 8;
                cpa16(sb + ((st * 4 + arr) * GTILE + row * GSTR + co) * 2,
                      g + (size_t)(r0 + row) * K + k0 + co);
            }
        }
    };

    float acc[4][4][4] = {};
    const int nIt = K / 32;

    load_stage(0, 0);
    cpa_commit();

    for (int it = 0; it < nIt; ++it) {
        int st = it & 1;
        if (it + 1 < nIt) {
            load_stage(st ^ 1, (it + 1) * 32);
            cpa_commit();
            cpa_wait<1>();
        } else {
            cpa_wait<0>();
        }
        __syncthreads();

        uint32_t uAh = sb + (st * 4 + 0) * GTILE * 2;
        uint32_t uAl = sb + (st * 4 + 1) * GTILE * 2;
        uint32_t uBh = sb + (st * 4 + 2) * GTILE * 2;
        uint32_t uBl = sb + (st * 4 + 3) * GTILE * 2;
#pragma unroll
        for (int kk = 0; kk < 2; ++kk) {
            uint32_t cb = kk * 16 + (lane >> 4) * 8;
            uint32_t bhf[2][4], blf[2][4];
#pragma unroll
            for (int bt = 0; bt < 2; ++bt) {
                uint32_t ro = (wn * 32 + bt * 16 + (lane & 15)) * GSTR + cb;
                ldsm4(bhf[bt], uBh + 2 * ro);
                ldsm4(blf[bt], uBl + 2 * ro);
            }
#pragma unroll
            for (int mp = 0; mp < 2; ++mp) {
                uint32_t ahf[2][4], alf[2][4];
#pragma unroll
                for (int i = 0; i < 2; ++i) {
                    uint32_t ro = (wm * 64 + (mp * 2 + i) * 16 + (lane & 15)) * GSTR + cb;
                    ldsm4(ahf[i], uAh + 2 * ro);
                    ldsm4(alf[i], uAl + 2 * ro);
                }
                // pass 1: hi*hi  (8 independent accumulators)
#pragma unroll
                for (int i = 0; i < 2; ++i)
#pragma unroll
                    for (int bt = 0; bt < 2; ++bt) {
                        mma16816(acc[mp * 2 + i][2 * bt],     ahf[i], bhf[bt][0], bhf[bt][2]);
                        mma16816(acc[mp * 2 + i][2 * bt + 1], ahf[i], bhf[bt][1], bhf[bt][3]);
                    }
                // pass 2: hi*lo
#pragma unroll
                for (int i = 0; i < 2; ++i)
#pragma unroll
                    for (int bt = 0; bt < 2; ++bt) {
                        mma16816(acc[mp * 2 + i][2 * bt],     ahf[i], blf[bt][0], blf[bt][2]);
                        mma16816(acc[mp * 2 + i][2 * bt + 1], ahf[i], blf[bt][1], blf[bt][3]);
                    }
                // pass 3: lo*hi
#pragma unroll
                for (int i = 0; i < 2; ++i)
#pragma unroll
                    for (int bt = 0; bt < 2; ++bt) {
                        mma16816(acc[mp * 2 + i][2 * bt],     alf[i], bhf[bt][0], bhf[bt][2]);
                        mma16816(acc[mp * 2 + i][2 * bt + 1], alf[i], bhf[bt][1], bhf[bt][3]);
                    }
            }
        }
        __syncthreads();
    }

    int r = lane >> 2, c2 = (lane & 3) * 2;
#pragma unroll
    for (int mi = 0; mi < 4; ++mi) {
        int row0 = bm + wm * 64 + mi * 16 + r;
#pragma unroll
        for (int ni = 0; ni < 4; ++ni) {
            int col = bn + wn * 32 + ni * 8 + c2;
            float bx = bias[col], by = bias[col + 1];
            float o00 = acc[mi][ni][0] + bx, o01 = acc[mi][ni][1] + by;
            float o10 = acc[mi][ni][2] + bx, o11 = acc[mi][ni][3] + by;
            if (SPLIT_OUT) {
                uint32_t hv, lv;
                pack2(o00, o01, hv, lv);
                *(uint32_t*)&Ch[(size_t)row0 * Nn + col] = hv;
                *(uint32_t*)&Cl[(size_t)row0 * Nn + col] = lv;
                pack2(o10, o11, hv, lv);
                *(uint32_t*)&Ch[(size_t)(row0 + 8) * Nn + col] = hv;
                *(uint32_t*)&Cl[(size_t)(row0 + 8) * Nn + col] = lv;
            } else {
                *(float2*)(Cout + (size_t)row0 * Nn + col) = make_float2(o00, o01);
                *(float2*)(Cout + (size_t)(row0 + 8) * Nn + col) = make_float2(o10, o11);
            }
        }
    }
}

// ---------------------------------------------------------------------------
// Flash attention, HMMA split-bf16, term-pass issue order.
// ---------------------------------------------------------------------------
#define ASTR 72
#define AQ (64 * ASTR)
#define ASSZ (4 * AQ + 128)
#define ATN_SMEM ((2 * AQ + 2 * ASSZ) * 2)

__global__ void __launch_bounds__(128, 2) attn_mma() {
    extern __shared__ __align__(16) __nv_bfloat16 sma[];
    uint32_t sb = smem_u32(sma);
    int tid = threadIdx.x, lane = tid & 31, wid = tid >> 5;
    int bhid = blockIdx.y;
    int b = bhid >> 4, h = bhid & 15;
    int q0 = blockIdx.x * 64;

    uint32_t uQh = sb;
    uint32_t uQl = sb + AQ * 2;

#pragma unroll
    for (int j = 0; j < 4; ++j) {
        int c = tid + j * 128;
        int row = c >> 3, co = (c & 7) * 8;
        size_t gi = (size_t)(b * NN + q0 + row) * C3 + h * HD + co;
        cpa16(uQh + (row * ASTR + co) * 2, g_qh + gi);
        cpa16(uQl + (row * ASTR + co) * 2, g_ql + gi);
    }
    cpa_commit();

    auto load_stage = [&](int st, int kt) {
        uint32_t base = sb + (2 * AQ + st * ASSZ) * 2;
#pragma unroll
        for (int j = 0; j < 4; ++j) {
            int c = tid + j * 128;
            int row = c >> 3, co = (c & 7) * 8;
            size_t gi = (size_t)(b * NN + kt + row) * C3 + h * HD + co;
            uint32_t so = (row * ASTR + co) * 2;
            cpa16(base + 0 * AQ * 2 + so, g_qh + gi + CC);
            cpa16(base + 1 * AQ * 2 + so, g_ql + gi + CC);
            cpa16(base + 2 * AQ * 2 + so, g_qh + gi + 2 * CC);
            cpa16(base + 3 * AQ * 2 + so, g_ql + gi + 2 * CC);
        }
        if (tid < 16)
            cpa16(base + 4 * AQ * 2 + tid * 16, g_gate + b * NN + kt + tid * 4);
    };

    load_stage(0, 0);
    cpa_commit();

    uint32_t qfh[4][4], qfl[4][4];
    cpa_wait<1>();
    __syncthreads();
#pragma unroll
    for (int kk = 0; kk < 4; ++kk) {
        uint32_t cb = kk * 16 + (lane >> 4) * 8;
        uint32_t qro = (wid * 16 + (lane & 15)) * ASTR + cb;
        ldsm4(qfh[kk], uQh + 2 * qro);
        ldsm4(qfl[kk], uQl + 2 * qro);
    }

    float m0 = -1e30f, m1 = -1e30f, l0s = 0.f, l1s = 0.f;
    float o[8][4] = {};

    for (int it = 0; it < NN / 64; ++it) {
        int st = it & 1;
        if (it + 1 < NN / 64) {
            load_stage(st ^ 1, (it + 1) * 64);
            cpa_commit();
            cpa_wait<1>();
        } else {
            cpa_wait<0>();
        }
        __syncthreads();

        uint32_t base = sb + (2 * AQ + st * ASSZ) * 2;
        uint32_t uKh = base, uKl = base + AQ * 2;
        uint32_t uVh = base + 2 * AQ * 2, uVl = base + 3 * AQ * 2;
        const float* gs = (const float*)(sma + (2 * AQ + st * ASSZ) + 4 * AQ);

        // ---- S = Q @ K^T: load all K frags for this kk, 3 term-passes ----
        float S[8][4] = {};
#pragma unroll
        for (int kk = 0; kk < 4; ++kk) {
            uint32_t cb = kk * 16 + (lane >> 4) * 8;
            uint32_t khf[4][4], klf[4][4];
#pragma unroll
            for (int nt2 = 0; nt2 < 4; ++nt2) {
                uint32_t kro = (nt2 * 16 + (lane & 15)) * ASTR + cb;
                ldsm4(khf[nt2], uKh + 2 * kro);
                ldsm4(klf[nt2], uKl + 2 * kro);
            }
#pragma unroll
            for (int nt2 = 0; nt2 < 4; ++nt2) {
                mma16816(S[2 * nt2],     qfh[kk], khf[nt2][0], khf[nt2][2]);
                mma16816(S[2 * nt2 + 1], qfh[kk], khf[nt2][1], khf[nt2][3]);
            }
#pragma unroll
            for (int nt2 = 0; nt2 < 4; ++nt2) {
                mma16816(S[2 * nt2],     qfh[kk], klf[nt2][0], klf[nt2][2]);
                mma16816(S[2 * nt2 + 1], qfh[kk], klf[nt2][1], klf[nt2][3]);
            }
#pragma unroll
            for (int nt2 = 0; nt2 < 4; ++nt2) {
                mma16816(S[2 * nt2],     qfl[kk], khf[nt2][0], khf[nt2][2]);
                mma16816(S[2 * nt2 + 1], qfl[kk], khf[nt2][1], khf[nt2][3]);
            }
        }
        // ---- scale * gate[key] ----
        int kc = (lane & 3) * 2;
#pragma unroll
        for (int nt = 0; nt < 8; ++nt) {
            float ga = gs[nt * 8 + kc] * 0.125f;
            float gb = gs[nt * 8 + kc + 1] * 0.125f;
            S[nt][0] *= ga; S[nt][1] *= gb;
            S[nt][2] *= ga; S[nt][3] *= gb;
        }
        // ---- online softmax ----
        float mx0 = m0, mx1 = m1;
#pragma unroll
        for (int nt = 0; nt < 8; ++nt) {
            mx0 = fmaxf(mx0, fmaxf(S[nt][0], S[nt][1]));
            mx1 = fmaxf(mx1, fmaxf(S[nt][2], S[nt][3]));
        }
        mx0 = fmaxf(mx0, __shfl_xor_sync(0xffffffffu, mx0, 1));
        mx0 = fmaxf(mx0, __shfl_xor_sync(0xffffffffu, mx0, 2));
        mx1 = fmaxf(mx1, __shfl_xor_sync(0xffffffffu, mx1, 1));
        mx1 = fmaxf(mx1, __shfl_xor_sync(0xffffffffu, mx1, 2));
        float c0 = __expf(m0 - mx0), c1 = __expf(m1 - mx1);
        m0 = mx0; m1 = mx1;
        l0s *= c0; l1s *= c1;
#pragma unroll
        for (int dt = 0; dt < 8; ++dt) {
            o[dt][0] *= c0; o[dt][1] *= c0;
            o[dt][2] *= c1; o[dt][3] *= c1;
        }
        float s0 = 0.f, s1 = 0.f;
#pragma unroll
        for (int nt = 0; nt < 8; ++nt) {
            S[nt][0] = __expf(S[nt][0] - mx0); s0 += S[nt][0];
            S[nt][1] = __expf(S[nt][1] - mx0); s0 += S[nt][1];
            S[nt][2] = __expf(S[nt][2] - mx1); s1 += S[nt][2];
            S[nt][3] = __expf(S[nt][3] - mx1); s1 += S[nt][3];
        }
        s0 += __shfl_xor_sync(0xffffffffu, s0, 1);
        s0 += __shfl_xor_sync(0xffffffffu, s0, 2);
        s1 += __shfl_xor_sync(0xffffffffu, s1, 1);
        s1 += __shfl_xor_sync(0xffffffffu, s1, 2);
        l0s += s0; l1s += s1;
        // ---- P -> A-frag repack, split hi/lo ----
        uint32_t ph[4][4], pl[4][4];
#pragma unroll
        for (int kb = 0; kb < 4; ++kb) {
            pack2(S[2 * kb][0],     S[2 * kb][1],     ph[kb][0], pl[kb][0]);
            pack2(S[2 * kb][2],     S[2 * kb][3],     ph[kb][1], pl[kb][1]);
            pack2(S[2 * kb + 1][0], S[2 * kb + 1][1], ph[kb][2], pl[kb][2]);
            pack2(S[2 * kb + 1][2], S[2 * kb + 1][3], ph[kb][3], pl[kb][3]);
        }
        // ---- O += P @ V: load all V frags per kb, 3 term-passes ----
#pragma unroll
        for (int kb = 0; kb < 4; ++kb) {
            uint32_t vhf[4][4], vlf[4][4];
#pragma unroll
            for (int dt2 = 0; dt2 < 4; ++dt2) {
                uint32_t vro = (kb * 16 + (lane & 15)) * ASTR
                             + dt2 * 16 + (lane >> 4) * 8;
                ldsm4t(vhf[dt2], uVh + 2 * vro);
                ldsm4t(vlf[dt2], uVl + 2 * vro);
            }
#pragma unroll
            for (int dt2 = 0; dt2 < 4; ++dt2) {
                mma16816(o[2 * dt2],     ph[kb], vhf[dt2][0], vhf[dt2][1]);
                mma16816(o[2 * dt2 + 1], ph[kb], vhf[dt2][2], vhf[dt2][3]);
            }
#pragma unroll
            for (int dt2 = 0; dt2 < 4; ++dt2) {
                mma16816(o[2 * dt2],     ph[kb], vlf[dt2][0], vlf[dt2][1]);
                mma16816(o[2 * dt2 + 1], ph[kb], vlf[dt2][2], vlf[dt2][3]);
            }
#pragma unroll
            for (int dt2 = 0; dt2 < 4; ++dt2) {
                mma16816(o[2 * dt2],     pl[kb], vhf[dt2][0], vhf[dt2][1]);
                mma16816(o[2 * dt2 + 1], pl[kb], vhf[dt2][2], vhf[dt2][3]);
            }
        }
        __syncthreads();
    }

    // Epilogue: normalize, write bf16 hi/lo for proj GEMM
    float i0 = 1.f / l0s, i1 = 1.f / l1s;
    int r = lane >> 2, c2 = (lane & 3) * 2;
    int row0 = q0 + wid * 16 + r;
#pragma unroll
    for (int dt = 0; dt < 8; ++dt) {
        int d = dt * 8 + c2;
        uint32_t hv, lv;
        size_t gi0 = (size_t)(b * NN + row0) * CC + h * HD + d;
        size_t gi1 = (size_t)(b * NN + row0 + 8) * CC + h * HD + d;
        pack2(o[dt][0] * i0, o[dt][1] * i0, hv, lv);
        *(uint32_t*)&g_ath[gi0] = hv;
        *(uint32_t*)&g_atl[gi0] = lv;
        pack2(o[dt][2] * i1, o[dt][3] * i1, hv, lv);
        *(uint32_t*)&g_ath[gi1] = hv;
        *(uint32_t*)&g_atl[gi1] = lv;
    }
}

// ---------------------------------------------------------------------------
// Launch
// ---------------------------------------------------------------------------
extern "C" void kernel_launch(void* const* d_in, const int* in_sizes, int n_in,
                              void* d_out, int out_size) {
    (void)in_sizes; (void)n_in; (void)out_size;
    const float* x      = (const float*)d_in[0];
    const float* smask  = (const float*)d_in[1];
    const float* qkv_w  = (const float*)d_in[2];
    const float* qkv_b  = (const float*)d_in[3];
    const float* proj_w = (const float*)d_in[4];
    const float* proj_b = (const float*)d_in[5];
    const float* g1_w   = (const float*)d_in[6];
    const float* g1_b   = (const float*)d_in[7];
    const float* g2_w   = (const float*)d_in[8];
    const float* g2_b   = (const float*)d_in[9];
    float* out = (float*)d_out;

    __nv_bfloat16 *xh, *xl, *wqh, *wql, *wph, *wpl, *qh, *ql, *ath, *atl;
    cudaGetSymbolAddress((void**)&xh,  g_xh);  cudaGetSymbolAddress((void**)&xl,  g_xl);
    cudaGetSymbolAddress((void**)&wqh, g_wqh); cudaGetSymbolAddress((void**)&wql, g_wql);
    cudaGetSymbolAddress((void**)&wph, g_wph); cudaGetSymbolAddress((void**)&wpl, g_wpl);
    cudaGetSymbolAddress((void**)&qh,  g_qh);  cudaGetSymbolAddress((void**)&ql,  g_ql);
    cudaGetSymbolAddress((void**)&ath, g_ath); cudaGetSymbolAddress((void**)&atl, g_atl);

    split_kernel<<<(TOK * CC / 4 + 255) / 256, 256>>>(x, xh, xl, TOK * CC / 4);
    split_kernel<<<(C3 * CC / 4 + 255) / 256, 256>>>(qkv_w, wqh, wql, C3 * CC / 4);
    split_kernel<<<(CC * CC / 4 + 255) / 256, 256>>>(proj_w, wph, wpl, CC * CC / 4);

    gate_kernel<<<(TOK * 32 + 255) / 256, 256>>>(smask, g1_w, g1_b, g2_w, g2_b);

    cudaFuncSetAttribute(gemm_mma<true>,
                         cudaFuncAttributeMaxDynamicSharedMemorySize, GEMM_SMEM);
    gemm_mma<true><<<dim3(C3 / 128, TOK / 128), 256, GEMM_SMEM>>>(
        xh, xl, wqh, wql, qkv_b, nullptr, qh, ql, C3, CC);

    cudaFuncSetAttribute(attn_mma,
                         cudaFuncAttributeMaxDynamicSharedMemorySize, ATN_SMEM);
    attn_mma<<<dim3(NN / 64, BB * HH), 128, ATN_SMEM>>>();

    cudaFuncSetAttribute(gemm_mma<false>,
                         cudaFuncAttributeMaxDynamicSharedMemorySize, GEMM_SMEM);
    gemm_mma<false><<<dim3(CC / 128, TOK / 128), 256, GEMM_SMEM>>>(
        ath, atl, wph, wpl, proj_b, out, nullptr, nullptr, CC, CC);
}

// round 8
// speedup vs baseline: 1.3098x; 1.2963x over previous
#include <cuda_runtime.h>
#include <cuda_bf16.h>
#include <cstdint>
#include <math.h>

// Problem constants
#define BB 2
#define NN 2048
#define CC 1024
#define HH 16
#define HD 64
#define GH 256
#define C3 3072
#define TOK (BB*NN)   // 4096

// Scratch (device globals: allocation-free)
__device__ float g_xt[(size_t)TOK * CC];    // x, tf32-rounded
__device__ float g_wqt[(size_t)C3 * CC];    // qkv_w, tf32-rounded
__device__ float g_wpt[(size_t)CC * CC];    // proj_w, tf32-rounded
__device__ __nv_bfloat16 g_qh[(size_t)TOK * C3], g_ql[(size_t)TOK * C3];
__device__ float g_att[(size_t)TOK * CC];   // attention out, tf32-rounded
__device__ float g_gate[TOK];

// ---------------------------------------------------------------------------
// Helpers
// ---------------------------------------------------------------------------
__device__ __forceinline__ uint32_t smem_u32(const void* p) {
    uint32_t a;
    asm("{ .reg .u64 t; cvta.to.shared.u64 t, %1; cvt.u32.u64 %0, t; }"
        : "=r"(a) : "l"(p));
    return a;
}
__device__ __forceinline__ void ldsm4(uint32_t* r, uint32_t addr) {
    asm volatile("ldmatrix.sync.aligned.m8n8.x4.shared.b16 {%0,%1,%2,%3}, [%4];"
                 : "=r"(r[0]), "=r"(r[1]), "=r"(r[2]), "=r"(r[3]) : "r"(addr));
}
__device__ __forceinline__ void ldsm4t(uint32_t* r, uint32_t addr) {
    asm volatile("ldmatrix.sync.aligned.m8n8.x4.trans.shared.b16 {%0,%1,%2,%3}, [%4];"
                 : "=r"(r[0]), "=r"(r[1]), "=r"(r[2]), "=r"(r[3]) : "r"(addr));
}
__device__ __forceinline__ void mma16816(float* d, const uint32_t* a,
                                         uint32_t b0, uint32_t b1) {
    asm("mma.sync.aligned.m16n8k16.row.col.f32.bf16.bf16.f32 "
        "{%0,%1,%2,%3}, {%4,%5,%6,%7}, {%8,%9}, {%0,%1,%2,%3};"
        : "+f"(d[0]), "+f"(d[1]), "+f"(d[2]), "+f"(d[3])
        : "r"(a[0]), "r"(a[1]), "r"(a[2]), "r"(a[3]), "r"(b0), "r"(b1));
}
__device__ __forceinline__ void mma_tf32(float* d, const uint32_t* a,
                                         uint32_t b0, uint32_t b1) {
    asm("mma.sync.aligned.m16n8k8.row.col.f32.tf32.tf32.f32 "
        "{%0,%1,%2,%3}, {%4,%5,%6,%7}, {%8,%9}, {%0,%1,%2,%3};"
        : "+f"(d[0]), "+f"(d[1]), "+f"(d[2]), "+f"(d[3])
        : "r"(a[0]), "r"(a[1]), "r"(a[2]), "r"(a[3]), "r"(b0), "r"(b1));
}
__device__ __forceinline__ void cpa16(uint32_t dst, const void* src) {
    asm volatile("cp.async.cg.shared.global [%0], [%1], 16;"
                 :: "r"(dst), "l"(src) : "memory");
}
__device__ __forceinline__ void cpa_commit() {
    asm volatile("cp.async.commit_group;" ::: "memory");
}
template <int N>
__device__ __forceinline__ void cpa_wait() {
    asm volatile("cp.async.wait_group %0;" :: "n"(N) : "memory");
}
__device__ __forceinline__ uint32_t to_tf32(float x) {
    uint32_t u;
    asm("cvt.rna.tf32.f32 %0, %1;" : "=r"(u) : "f"(x));
    return u;
}
__device__ __forceinline__ void pack2(float x, float y, uint32_t& hi, uint32_t& lo) {
    __nv_bfloat162 h = __floats2bfloat162_rn(x, y);
    float2 hf = __bfloat1622float2(h);
    __nv_bfloat162 l = __floats2bfloat162_rn(x - hf.x, y - hf.y);
    hi = *reinterpret_cast<uint32_t*>(&h);
    lo = *reinterpret_cast<uint32_t*>(&l);
}

// ---------------------------------------------------------------------------
// Prep: fp32 -> tf32-rounded fp32
// ---------------------------------------------------------------------------
__global__ void tf32_kernel(const float* __restrict__ s,
                            float* __restrict__ d, int n4) {
    int i = blockIdx.x * blockDim.x + threadIdx.x;
    if (i >= n4) return;
    float4 v = ((const float4*)s)[i];
    uint4 o;
    o.x = to_tf32(v.x); o.y = to_tf32(v.y);
    o.z = to_tf32(v.z); o.w = to_tf32(v.w);
    ((uint4*)d)[i] = o;
}

// ---------------------------------------------------------------------------
// Gate MLP: one warp per token
// ---------------------------------------------------------------------------
__global__ void gate_kernel(const float* __restrict__ sm,
                            const float* __restrict__ g1w,
                            const float* __restrict__ g1b,
                            const float* __restrict__ g2w,
                            const float* __restrict__ g2b) {
    int w = (blockIdx.x * blockDim.x + threadIdx.x) >> 5;
    int lane = threadIdx.x & 31;
    if (w >= TOK) return;
    float m = sm[w];
    float acc = 0.f;
#pragma unroll
    for (int j = lane; j < GH; j += 32) {
        float h = fmaxf(fmaf(m, g1w[j], g1b[j]), 0.f);
        acc = fmaf(h, g2w[j], acc);
    }
#pragma unroll
    for (int o = 16; o; o >>= 1) acc += __shfl_xor_sync(0xffffffffu, acc, o);
    if (lane == 0) g_gate[w] = 1.f / (1.f + __expf(-(acc + g2b[0])));
}

// ---------------------------------------------------------------------------
// TF32 1-pass GEMM: C[m,n] = sum_k A[m,k]*B[n,k] (+bias)
// Block 128x128, BK=32, 8 warps (2x4), warp 64x32, 2-stage cp.async,
// single barrier per iter. ldmatrix used in 8x4-b32 view for tf32 frags.
// ---------------------------------------------------------------------------
#define GS 36                    // fp32 row stride (144 B; 8 rows span all banks)
#define GSTAGE (128 * GS)        // fp32 elems per tile per stage
#define GEMM_SMEM (2 * 2 * GSTAGE * 4)   // 73728 bytes

template <bool SPLIT_OUT>
__global__ void __launch_bounds__(256, 2) gemm_tf32(
    const float* __restrict__ A, const float* __restrict__ B,
    const float* __restrict__ bias,
    float* __restrict__ Cout,
    __nv_bfloat16* __restrict__ Ch, __nv_bfloat16* __restrict__ Cl,
    int Nn, int K) {
    extern __shared__ __align__(16) float smf[];
    uint32_t sb = smem_u32(smf);
    int tid = threadIdx.x, lane = tid & 31, wid = tid >> 5;
    int wm = wid >> 2, wn = wid & 3;
    int bm = blockIdx.y * 128, bn = blockIdx.x * 128;

    auto load_stage = [&](int st, int k0) {
        uint32_t base = sb + st * 2 * GSTAGE * 4;
#pragma unroll
        for (int j = 0; j < 4; ++j) {
            int c = tid + j * 256;
            int row = c >> 3, c16 = c & 7;
            cpa16(base + row * (GS * 4) + c16 * 16,
                  A + (size_t)(bm + row) * K + k0 + c16 * 4);
        }
#pragma unroll
        for (int j = 0; j < 4; ++j) {
            int c = tid + j * 256;
            int row = c >> 3, c16 = c & 7;
            cpa16(base + GSTAGE * 4 + row * (GS * 4) + c16 * 16,
                  B + (size_t)(bn + row) * K + k0 + c16 * 4);
        }
    };

    float acc[4][4][4] = {};
    const int nIt = K / 32;

    load_stage(0, 0);
    cpa_commit();

    int mat = lane >> 3, l7 = lane & 7;
    for (int it = 0; it < nIt; ++it) {
        cpa_wait<0>();
        __syncthreads();   // all warps done with the stage being overwritten
        if (it + 1 < nIt) { load_stage((it + 1) & 1, (it + 1) * 32); cpa_commit(); }

        uint32_t uA = sb + (it & 1) * 2 * GSTAGE * 4;
        uint32_t uB = uA + GSTAGE * 4;
#pragma unroll
        for (int k8 = 0; k8 < 4; ++k8) {
            int kc = k8 * 8;
            uint32_t af[4][4], bf[2][4];
            // B frags: 4 n-tiles via 2 ldsm4. matrix m: row n0+((m&2)?8:0)+l7, col kc+((m&1)?4:0)
#pragma unroll
            for (int bp = 0; bp < 2; ++bp) {
                int row = wn * 32 + bp * 16 + ((mat & 2) ? 8 : 0) + l7;
                int col = kc + ((mat & 1) ? 4 : 0);
                ldsm4(bf[bp], uB + row * (GS * 4) + col * 4);
            }
            // A frags: 4 m-tiles. matrix m: row r0+((m&1)?8:0)+l7, col kc+((m&2)?4:0)
#pragma unroll
            for (int mi = 0; mi < 4; ++mi) {
                int row = wm * 64 + mi * 16 + ((mat & 1) ? 8 : 0) + l7;
                int col = kc + ((mat & 2) ? 4 : 0);
                ldsm4(af[mi], uA + row * (GS * 4) + col * 4);
            }
#pragma unroll
            for (int mi = 0; mi < 4; ++mi)
#pragma unroll
                for (int nt = 0; nt < 4; ++nt)
                    mma_tf32(acc[mi][nt], af[mi],
                             bf[nt >> 1][(nt & 1) * 2], bf[nt >> 1][(nt & 1) * 2 + 1]);
        }
    }

    int r = lane >> 2, c2 = (lane & 3) * 2;
#pragma unroll
    for (int mi = 0; mi < 4; ++mi) {
        int row0 = bm + wm * 64 + mi * 16 + r;
#pragma unroll
        for (int ni = 0; ni < 4; ++ni) {
            int col = bn + wn * 32 + ni * 8 + c2;
            float bx = bias[col], by = bias[col + 1];
            float o00 = acc[mi][ni][0] + bx, o01 = acc[mi][ni][1] + by;
            float o10 = acc[mi][ni][2] + bx, o11 = acc[mi][ni][3] + by;
            if (SPLIT_OUT) {
                uint32_t hv, lv;
                pack2(o00, o01, hv, lv);
                *(uint32_t*)&Ch[(size_t)row0 * Nn + col] = hv;
                *(uint32_t*)&Cl[(size_t)row0 * Nn + col] = lv;
                pack2(o10, o11, hv, lv);
                *(uint32_t*)&Ch[(size_t)(row0 + 8) * Nn + col] = hv;
                *(uint32_t*)&Cl[(size_t)(row0 + 8) * Nn + col] = lv;
            } else {
                *(float2*)(Cout + (size_t)row0 * Nn + col) = make_float2(o00, o01);
                *(float2*)(Cout + (size_t)(row0 + 8) * Nn + col) = make_float2(o10, o11);
            }
        }
    }
}

// ---------------------------------------------------------------------------
// Flash attention, HMMA split-bf16 (unchanged core), epilogue -> tf32 fp32.
// ---------------------------------------------------------------------------
#define ASTR 72
#define AQ (64 * ASTR)
#define ASSZ (4 * AQ + 128)
#define ATN_SMEM ((2 * AQ + 2 * ASSZ) * 2)

__global__ void __launch_bounds__(128, 2) attn_mma() {
    extern __shared__ __align__(16) __nv_bfloat16 sma[];
    uint32_t sb = smem_u32(sma);
    int tid = threadIdx.x, lane = tid & 31, wid = tid >> 5;
    int bhid = blockIdx.y;
    int b = bhid >> 4, h = bhid & 15;
    int q0 = blockIdx.x * 64;

    uint32_t uQh = sb;
    uint32_t uQl = sb + AQ * 2;

#pragma unroll
    for (int j = 0; j < 4; ++j) {
        int c = tid + j * 128;
        int row = c >> 3, co = (c & 7) * 8;
        size_t gi = (size_t)(b * NN + q0 + row) * C3 + h * HD + co;
        cpa16(uQh + (row * ASTR + co) * 2, g_qh + gi);
        cpa16(uQl + (row * ASTR + co) * 2, g_ql + gi);
    }
    cpa_commit();

    auto load_stage = [&](int st, int kt) {
        uint32_t base = sb + (2 * AQ + st * ASSZ) * 2;
#pragma unroll
        for (int j = 0; j < 4; ++j) {
            int c = tid + j * 128;
            int row = c >> 3, co = (c & 7) * 8;
            size_t gi = (size_t)(b * NN + kt + row) * C3 + h * HD + co;
            uint32_t so = (row * ASTR + co) * 2;
            cpa16(base + 0 * AQ * 2 + so, g_qh + gi + CC);
            cpa16(base + 1 * AQ * 2 + so, g_ql + gi + CC);
            cpa16(base + 2 * AQ * 2 + so, g_qh + gi + 2 * CC);
            cpa16(base + 3 * AQ * 2 + so, g_ql + gi + 2 * CC);
        }
        if (tid < 16)
            cpa16(base + 4 * AQ * 2 + tid * 16, g_gate + b * NN + kt + tid * 4);
    };

    load_stage(0, 0);
    cpa_commit();

    uint32_t qfh[4][4], qfl[4][4];
    cpa_wait<1>();
    __syncthreads();
#pragma unroll
    for (int kk = 0; kk < 4; ++kk) {
        uint32_t cb = kk * 16 + (lane >> 4) * 8;
        uint32_t qro = (wid * 16 + (lane & 15)) * ASTR + cb;
        ldsm4(qfh[kk], uQh + 2 * qro);
        ldsm4(qfl[kk], uQl + 2 * qro);
    }

    float m0 = -1e30f, m1 = -1e30f, l0s = 0.f, l1s = 0.f;
    float o[8][4] = {};

    for (int it = 0; it < NN / 64; ++it) {
        int st = it & 1;
        if (it + 1 < NN / 64) {
            load_stage(st ^ 1, (it + 1) * 64);
            cpa_commit();
            cpa_wait<1>();
        } else {
            cpa_wait<0>();
        }
        __syncthreads();

        uint32_t base = sb + (2 * AQ + st * ASSZ) * 2;
        uint32_t uKh = base, uKl = base + AQ * 2;
        uint32_t uVh = base + 2 * AQ * 2, uVl = base + 3 * AQ * 2;
        const float* gs = (const float*)(sma + (2 * AQ + st * ASSZ) + 4 * AQ);

        float S[8][4] = {};
#pragma unroll
        for (int kk = 0; kk < 4; ++kk) {
            uint32_t cb = kk * 16 + (lane >> 4) * 8;
            uint32_t khf[4][4], klf[4][4];
#pragma unroll
            for (int nt2 = 0; nt2 < 4; ++nt2) {
                uint32_t kro = (nt2 * 16 + (lane & 15)) * ASTR + cb;
                ldsm4(khf[nt2], uKh + 2 * kro);
                ldsm4(klf[nt2], uKl + 2 * kro);
            }
#pragma unroll
            for (int nt2 = 0; nt2 < 4; ++nt2) {
                mma16816(S[2 * nt2],     qfh[kk], khf[nt2][0], khf[nt2][2]);
                mma16816(S[2 * nt2 + 1], qfh[kk], khf[nt2][1], khf[nt2][3]);
            }
#pragma unroll
            for (int nt2 = 0; nt2 < 4; ++nt2) {
                mma16816(S[2 * nt2],     qfh[kk], klf[nt2][0], klf[nt2][2]);
                mma16816(S[2 * nt2 + 1], qfh[kk], klf[nt2][1], klf[nt2][3]);
            }
#pragma unroll
            for (int nt2 = 0; nt2 < 4; ++nt2) {
                mma16816(S[2 * nt2],     qfl[kk], khf[nt2][0], khf[nt2][2]);
                mma16816(S[2 * nt2 + 1], qfl[kk], khf[nt2][1], khf[nt2][3]);
            }
        }
        int kc = (lane & 3) * 2;
#pragma unroll
        for (int nt = 0; nt < 8; ++nt) {
            float ga = gs[nt * 8 + kc] * 0.125f;
            float gb = gs[nt * 8 + kc + 1] * 0.125f;
            S[nt][0] *= ga; S[nt][1] *= gb;
            S[nt][2] *= ga; S[nt][3] *= gb;
        }
        float mx0 = m0, mx1 = m1;
#pragma unroll
        for (int nt = 0; nt < 8; ++nt) {
            mx0 = fmaxf(mx0, fmaxf(S[nt][0], S[nt][1]));
            mx1 = fmaxf(mx1, fmaxf(S[nt][2], S[nt][3]));
        }
        mx0 = fmaxf(mx0, __shfl_xor_sync(0xffffffffu, mx0, 1));
        mx0 = fmaxf(mx0, __shfl_xor_sync(0xffffffffu, mx0, 2));
        mx1 = fmaxf(mx1, __shfl_xor_sync(0xffffffffu, mx1, 1));
        mx1 = fmaxf(mx1, __shfl_xor_sync(0xffffffffu, mx1, 2));
        float c0 = __expf(m0 - mx0), c1 = __expf(m1 - mx1);
        m0 = mx0; m1 = mx1;
        l0s *= c0; l1s *= c1;
#pragma unroll
        for (int dt = 0; dt < 8; ++dt) {
            o[dt][0] *= c0; o[dt][1] *= c0;
            o[dt][2] *= c1; o[dt][3] *= c1;
        }
        float s0 = 0.f, s1 = 0.f;
#pragma unroll
        for (int nt = 0; nt < 8; ++nt) {
            S[nt][0] = __expf(S[nt][0] - mx0); s0 += S[nt][0];
            S[nt][1] = __expf(S[nt][1] - mx0); s0 += S[nt][1];
            S[nt][2] = __expf(S[nt][2] - mx1); s1 += S[nt][2];
            S[nt][3] = __expf(S[nt][3] - mx1); s1 += S[nt][3];
        }
        s0 += __shfl_xor_sync(0xffffffffu, s0, 1);
        s0 += __shfl_xor_sync(0xffffffffu, s0, 2);
        s1 += __shfl_xor_sync(0xffffffffu, s1, 1);
        s1 += __shfl_xor_sync(0xffffffffu, s1, 2);
        l0s += s0; l1s += s1;
        uint32_t ph[4][4], pl[4][4];
#pragma unroll
        for (int kb = 0; kb < 4; ++kb) {
            pack2(S[2 * kb][0],     S[2 * kb][1],     ph[kb][0], pl[kb][0]);
            pack2(S[2 * kb][2],     S[2 * kb][3],     ph[kb][1], pl[kb][1]);
            pack2(S[2 * kb + 1][0], S[2 * kb + 1][1], ph[kb][2], pl[kb][2]);
            pack2(S[2 * kb + 1][2], S[2 * kb + 1][3], ph[kb][3], pl[kb][3]);
        }
#pragma unroll
        for (int kb = 0; kb < 4; ++kb) {
            uint32_t vhf[4][4], vlf[4][4];
#pragma unroll
            for (int dt2 = 0; dt2 < 4; ++dt2) {
                uint32_t vro = (kb * 16 + (lane & 15)) * ASTR
                             + dt2 * 16 + (lane >> 4) * 8;
                ldsm4t(vhf[dt2], uVh + 2 * vro);
                ldsm4t(vlf[dt2], uVl + 2 * vro);
            }
#pragma unroll
            for (int dt2 = 0; dt2 < 4; ++dt2) {
                mma16816(o[2 * dt2],     ph[kb], vhf[dt2][0], vhf[dt2][1]);
                mma16816(o[2 * dt2 + 1], ph[kb], vhf[dt2][2], vhf[dt2][3]);
            }
#pragma unroll
            for (int dt2 = 0; dt2 < 4; ++dt2) {
                mma16816(o[2 * dt2],     ph[kb], vlf[dt2][0], vlf[dt2][1]);
                mma16816(o[2 * dt2 + 1], ph[kb], vlf[dt2][2], vlf[dt2][3]);
            }
#pragma unroll
            for (int dt2 = 0; dt2 < 4; ++dt2) {
                mma16816(o[2 * dt2],     pl[kb], vhf[dt2][0], vhf[dt2][1]);
                mma16816(o[2 * dt2 + 1], pl[kb], vhf[dt2][2], vhf[dt2][3]);
            }
        }
        __syncthreads();
    }

    // Epilogue: normalize, tf32-round, write fp32 for proj GEMM
    float i0 = 1.f / l0s, i1 = 1.f / l1s;
    int r = lane >> 2, c2 = (lane & 3) * 2;
    int row0 = q0 + wid * 16 + r;
#pragma unroll
    for (int dt = 0; dt < 8; ++dt) {
        int d = dt * 8 + c2;
        size_t gi0 = (size_t)(b * NN + row0) * CC + h * HD + d;
        size_t gi1 = (size_t)(b * NN + row0 + 8) * CC + h * HD + d;
        uint2 w0 = make_uint2(to_tf32(o[dt][0] * i0), to_tf32(o[dt][1] * i0));
        uint2 w1 = make_uint2(to_tf32(o[dt][2] * i1), to_tf32(o[dt][3] * i1));
        *(uint2*)&g_att[gi0] = w0;
        *(uint2*)&g_att[gi1] = w1;
    }
}

// ---------------------------------------------------------------------------
// Launch
// ---------------------------------------------------------------------------
extern "C" void kernel_launch(void* const* d_in, const int* in_sizes, int n_in,
                              void* d_out, int out_size) {
    (void)in_sizes; (void)n_in; (void)out_size;
    const float* x      = (const float*)d_in[0];
    const float* smask  = (const float*)d_in[1];
    const float* qkv_w  = (const float*)d_in[2];
    const float* qkv_b  = (const float*)d_in[3];
    const float* proj_w = (const float*)d_in[4];
    const float* proj_b = (const float*)d_in[5];
    const float* g1_w   = (const float*)d_in[6];
    const float* g1_b   = (const float*)d_in[7];
    const float* g2_w   = (const float*)d_in[8];
    const float* g2_b   = (const float*)d_in[9];
    float* out = (float*)d_out;

    float *xt, *wqt, *wpt, *att;
    __nv_bfloat16 *qh, *ql;
    cudaGetSymbolAddress((void**)&xt,  g_xt);
    cudaGetSymbolAddress((void**)&wqt, g_wqt);
    cudaGetSymbolAddress((void**)&wpt, g_wpt);
    cudaGetSymbolAddress((void**)&att, g_att);
    cudaGetSymbolAddress((void**)&qh,  g_qh);
    cudaGetSymbolAddress((void**)&ql,  g_ql);

    // 0. tf32-round inputs
    tf32_kernel<<<(TOK * CC / 4 + 255) / 256, 256>>>(x, xt, TOK * CC / 4);
    tf32_kernel<<<(C3 * CC / 4 + 255) / 256, 256>>>(qkv_w, wqt, C3 * CC / 4);
    tf32_kernel<<<(CC * CC / 4 + 255) / 256, 256>>>(proj_w, wpt, CC * CC / 4);

    // 1. gate
    gate_kernel<<<(TOK * 32 + 255) / 256, 256>>>(smask, g1_w, g1_b, g2_w, g2_b);

    // 2. qkv = x @ qkv_w^T + qkv_b  (tf32 1-pass; bf16 hi/lo out for attn)
    cudaFuncSetAttribute(gemm_tf32<true>,
                         cudaFuncAttributeMaxDynamicSharedMemorySize, GEMM_SMEM);
    gemm_tf32<true><<<dim3(C3 / 128, TOK / 128), 256, GEMM_SMEM>>>(
        xt, wqt, qkv_b, nullptr, qh, ql, C3, CC);

    // 3. attention (bf16 3-term, unchanged)
    cudaFuncSetAttribute(attn_mma,
                         cudaFuncAttributeMaxDynamicSharedMemorySize, ATN_SMEM);
    attn_mma<<<dim3(NN / 64, BB * HH), 128, ATN_SMEM>>>();

    // 4. out = att @ proj_w^T + proj_b  (tf32 1-pass, fp32 out)
    cudaFuncSetAttribute(gemm_tf32<false>,
                         cudaFuncAttributeMaxDynamicSharedMemorySize, GEMM_SMEM);
    gemm_tf32<false><<<dim3(CC / 128, TOK / 128), 256, GEMM_SMEM>>>(
        att, wpt, proj_b, out, nullptr, nullptr, CC, CC);
}